// round 13
// baseline (speedup 1.0000x reference)
#include <cuda_runtime.h>
#include <cstdint>

// ---------------------------------------------------------------------------
// Threefry-2x32, FULL 20 rounds + 6 key injections (bit-exact JAX).
// ---------------------------------------------------------------------------
#define TF_ROUND(r) do { x0 += x1; x1 = (x1 << (r)) | (x1 >> (32 - (r))); x1 ^= x0; } while (0)

__host__ __device__ __forceinline__ void tf2x32(uint32_t k0, uint32_t k1,
                                                uint32_t x0, uint32_t x1,
                                                uint32_t& o0, uint32_t& o1) {
    uint32_t k2 = k0 ^ k1 ^ 0x1BD11BDAu;
    x0 += k0; x1 += k1;
    TF_ROUND(13); TF_ROUND(15); TF_ROUND(26); TF_ROUND(6);
    x0 += k1; x1 += k2 + 1u;
    TF_ROUND(17); TF_ROUND(29); TF_ROUND(16); TF_ROUND(24);
    x0 += k2; x1 += k0 + 2u;
    TF_ROUND(13); TF_ROUND(15); TF_ROUND(26); TF_ROUND(6);
    x0 += k0; x1 += k1 + 3u;
    TF_ROUND(17); TF_ROUND(29); TF_ROUND(16); TF_ROUND(24);
    x0 += k1; x1 += k2 + 4u;
    TF_ROUND(13); TF_ROUND(15); TF_ROUND(26); TF_ROUND(6);
    x0 += k2; x1 += k0 + 5u;
    o0 = x0; o1 = x1;
}

__device__ __forceinline__ uint32_t tfbits(uint32_t k0, uint32_t k1, uint32_t j) {
    uint32_t o0, o1;
    tf2x32(k0, k1, 0u, j, o0, o1);
    return o0 ^ o1;
}

__device__ __forceinline__ float jax_uniform(uint32_t bits) {
    const float TINY = 1.17549435e-38f;
    float f = __uint_as_float((bits >> 9) | 0x3f800000u) - 1.0f;
    return fmaxf(TINY, f + TINY);
}

__device__ __forceinline__ bool decide(float c0, float c1, uint32_t b0, uint32_t b1) {
    if (c0 == c1) return (b1 >> 9) > (b0 >> 9);
    float g0 = -logf(-logf(jax_uniform(b0)));
    float g1 = -logf(-logf(jax_uniform(b1)));
    return (c1 + g1) > (c0 + g0);
}

// ---------------------------------------------------------------------------
#define B_SZ  128
#define F0    1024
#define F1    512

__device__ int      g_op0[F1];
__device__ int      g_op1[F0];
// masks TRANSPOSED: g_mask0[w][o] (w<32,o<512), g_mask1[w][o] (w<16,o<1024)
__device__ uint32_t g_mask0[(F0 / 32) * F1];   // 64 KB
__device__ uint32_t g_mask1[(F1 / 32) * F0];   // 64 KB

// shfl compare-exchange for one (k, j<=16) bitonic phase; s = element index.
__device__ __forceinline__ unsigned long long bitonic_shfl_step(
        unsigned long long v, int s, int k, int j) {
    unsigned long long pv = __shfl_xor_sync(0xffffffffu, v, j);
    bool up = ((s & k) == 0);
    bool keepMin = (((s & j) == 0) == up);
    unsigned long long lo = v < pv ? v : pv;
    unsigned long long hi = v < pv ? pv : v;
    return keepMin ? lo : hi;
}

// ---------------------------------------------------------------------------
// k_masks (512 blocks, 512 threads): pure threefry mask generation.
//   blocks [0,256)   : layer-0 masks (out=512, in=1024)
//   blocks [256,512) : layer-1 masks (out=1024, in=512)
// ---------------------------------------------------------------------------
__global__ __launch_bounds__(512) void k_masks(
        const float* __restrict__ etc0, const float* __restrict__ otc0,
        const float* __restrict__ etc1, const float* __restrict__ otc1,
        uint32_t op0k0, uint32_t op0k1, uint32_t e0k0, uint32_t e0k1,
        uint32_t op1k0, uint32_t op1k1, uint32_t e1k0, uint32_t e1k1) {
    int bid = blockIdx.x;
    int tid = threadIdx.x;
    int warp = tid >> 5, lane = tid & 31;

    int o, wslice, log2in, outn;
    const float* etc; const float* otc;
    uint32_t ek0, ek1, opk0, opk1;
    uint32_t* maskb; int* oparr;
    if (bid < 256) {              // layer 0: 8 warp-slices per o, 4 edges/thr
        o = bid * 2 + (warp >> 3); wslice = warp & 7;
        log2in = 10; outn = F1; etc = etc0; otc = otc0;
        ek0 = e0k0; ek1 = e0k1; opk0 = op0k0; opk1 = op0k1;
        maskb = g_mask0; oparr = g_op0;
    } else {                      // layer 1: 4 warp-slices per o, 4 edges/thr
        int q = bid - 256;
        o = q * 4 + (warp >> 2); wslice = warp & 3;
        log2in = 9; outn = F0; etc = etc1; otc = otc1;
        ek0 = e1k0; ek1 = e1k1; opk0 = op1k0; opk1 = op1k1;
        maskb = g_mask1; oparr = g_op1;
    }

    uint32_t jv = tfbits(opk0, opk1, (uint32_t)(2 * o) + (uint32_t)(lane & 1));
    uint32_t ob0 = __shfl_sync(0xffffffffu, jv, 0);
    uint32_t ob1 = __shfl_sync(0xffffffffu, jv, 1);
    int op = decide(otc[2 * o], otc[2 * o + 1], ob0, ob1) ? 1 : 0;
    if (wslice == 0 && lane == 0) oparr[o] = op;

    uint32_t mbase = ((uint32_t)(o * 2 + op)) << log2in;
    const float2* etc2 = (const float2*)etc;

    #pragma unroll
    for (int c = 0; c < 4; ++c) {
        int i = wslice * 128 + c * 32 + lane;
        uint32_t m = mbase + (uint32_t)i;
        uint32_t b0 = tfbits(ek0, ek1, 2u * m);
        uint32_t b1 = tfbits(ek0, ek1, 2u * m + 1u);
        float2 cc = etc2[m];
        bool sel = decide(cc.x, cc.y, b0, b1);
        unsigned msk = __ballot_sync(0xffffffffu, sel);
        if (lane == 0) maskb[(i >> 5) * outn + o] = msk;   // transposed
    }
}

// ---------------------------------------------------------------------------
// Batched per-thread probe; masks from global, transposed [w][o]:
// w warp-uniform, o lane-linear -> fully coalesced LDG (L2-hot).
// ---------------------------------------------------------------------------
__device__ __forceinline__ float probe8g(const unsigned long long* __restrict__ a,
                                         int n, const uint32_t* __restrict__ mt,
                                         int outn, int o, int op) {
    float res;
    if (op == 0) {
        res = 1.0f;
        for (int base = 0; base < n; base += 8) {
            unsigned long long kv[8];
            uint32_t w[8];
            #pragma unroll
            for (int t = 0; t < 8; ++t) kv[t] = a[base + t];
            #pragma unroll
            for (int t = 0; t < 8; ++t) {
                unsigned idx = (unsigned)kv[t];
                w[t] = __ldg(mt + (idx >> 5) * outn + o) >> (idx & 31);
            }
            bool found = false;
            #pragma unroll
            for (int t = 0; t < 8; ++t)
                if (!found && (w[t] & 1u)) {
                    res = __uint_as_float((unsigned)(kv[t] >> 32));
                    found = true;
                }
            if (found) break;
        }
    } else {
        res = 0.0f;
        for (int base = n - 8; base >= 0; base -= 8) {
            unsigned long long kv[8];
            uint32_t w[8];
            #pragma unroll
            for (int t = 0; t < 8; ++t) kv[t] = a[base + 7 - t];
            #pragma unroll
            for (int t = 0; t < 8; ++t) {
                unsigned idx = (unsigned)kv[t];
                w[t] = __ldg(mt + (idx >> 5) * outn + o) >> (idx & 31);
            }
            bool found = false;
            #pragma unroll
            for (int t = 0; t < 8; ++t)
                if (!found && (w[t] & 1u)) {
                    res = __uint_as_float((unsigned)(kv[t] >> 32));
                    found = true;
                }
            if (found) break;
        }
    }
    return res;
}

// ---------------------------------------------------------------------------
// k_fused (128 blocks, 512 threads): per batch row, everything:
//  1) load raw x row, build keys
//  2) bitonic sort 1024 in smem (hybrid shfl)
//  3) probe layer 0 (1 neuron/thread)
//  4) bitonic sort 512 hidden keys
//  5) probe layer 1 (2 neurons/thread) -> out
// ---------------------------------------------------------------------------
__global__ __launch_bounds__(512) void k_fused(const float* __restrict__ x,
                                               float* __restrict__ out) {
    __shared__ unsigned long long a[1024];
    __shared__ unsigned long long hk[512];
    int row = blockIdx.x;
    int tid = threadIdx.x;

    // 1) load + build keys (2 per thread)
    float v0 = fmaxf(x[(size_t)row * F0 + tid], 0.0f);
    float v1 = fmaxf(x[(size_t)row * F0 + tid + 512], 0.0f);
    unsigned long long e0 = ((unsigned long long)__float_as_uint(v0) << 32) | (unsigned)tid;
    unsigned long long e1 = ((unsigned long long)__float_as_uint(v1) << 32) | (unsigned)(tid + 512);

    // 2) bitonic 1024: k=2..32 in registers
    #pragma unroll
    for (int k = 2; k <= 32; k <<= 1)
        #pragma unroll
        for (int j = k >> 1; j > 0; j >>= 1) {
            e0 = bitonic_shfl_step(e0, tid, k, j);
            e1 = bitonic_shfl_step(e1, tid + 512, k, j);
        }
    a[tid] = e0; a[tid + 512] = e1;
    __syncthreads();

    #pragma unroll
    for (int k = 64; k <= 512; k <<= 1) {
        for (int j = k >> 1; j >= 32; j >>= 1) {
            #pragma unroll
            for (int r = 0; r < 2; ++r) {
                int s = tid + r * 512;
                int l = s ^ j;
                if (l > s) {
                    bool up = ((s & k) == 0);
                    unsigned long long va = a[s], vb = a[l];
                    if ((va > vb) == up) { a[s] = vb; a[l] = va; }
                }
            }
            __syncthreads();
        }
        e0 = a[tid]; e1 = a[tid + 512];
        #pragma unroll
        for (int j = 16; j > 0; j >>= 1) {
            e0 = bitonic_shfl_step(e0, tid, k, j);
            e1 = bitonic_shfl_step(e1, tid + 512, k, j);
        }
        a[tid] = e0; a[tid + 512] = e1;
        __syncthreads();
    }

    // k = 1024: j=512 intra-thread, j=256..32 smem, j<=16 registers
    e0 = a[tid]; e1 = a[tid + 512];
    if (e0 > e1) { unsigned long long t = e0; e0 = e1; e1 = t; }
    a[tid] = e0; a[tid + 512] = e1;
    __syncthreads();
    for (int j = 256; j >= 32; j >>= 1) {
        #pragma unroll
        for (int r = 0; r < 2; ++r) {
            int s = tid + r * 512;
            int l = s ^ j;
            if (l > s) {
                unsigned long long va = a[s], vb = a[l];
                if (va > vb) { a[s] = vb; a[l] = va; }
            }
        }
        __syncthreads();
    }
    e0 = a[tid]; e1 = a[tid + 512];
    #pragma unroll
    for (int j = 16; j > 0; j >>= 1) {
        e0 = bitonic_shfl_step(e0, tid, 1024, j);
        e1 = bitonic_shfl_step(e1, tid + 512, 1024, j);
    }
    a[tid] = e0; a[tid + 512] = e1;
    __syncthreads();

    // 3) probe layer 0 (1 neuron per thread)
    unsigned long long v;
    {
        int o = tid;
        int op = g_op0[o];
        float res = probe8g(a, F0, g_mask0, F1, o, op);
        v = ((unsigned long long)__float_as_uint(res) << 32) | (unsigned)o;
    }

    // 4) bitonic sort 512 hidden keys
    #pragma unroll
    for (int k = 2; k <= 32; k <<= 1)
        #pragma unroll
        for (int j = k >> 1; j > 0; j >>= 1)
            v = bitonic_shfl_step(v, tid, k, j);

    hk[tid] = v;
    __syncthreads();

    #pragma unroll
    for (int k = 64; k <= 512; k <<= 1) {
        for (int j = k >> 1; j >= 32; j >>= 1) {
            int s = tid, l = tid ^ j;
            if (l > s) {
                bool up = ((s & k) == 0);
                unsigned long long va = hk[s], vb = hk[l];
                if ((va > vb) == up) { hk[s] = vb; hk[l] = va; }
            }
            __syncthreads();
        }
        v = hk[tid];
        #pragma unroll
        for (int j = 16; j > 0; j >>= 1)
            v = bitonic_shfl_step(v, tid, k, j);
        hk[tid] = v;
        __syncthreads();
    }

    // 5) probe layer 1 (2 neurons per thread) -> out
    #pragma unroll
    for (int rep = 0; rep < 2; ++rep) {
        int o = tid + rep * 512;
        int op = g_op1[o];
        float res = probe8g(hk, F1, g_mask1, F0, o, op);
        out[(size_t)row * F0 + o] = res;
    }
}

// ---------------------------------------------------------------------------
extern "C" void kernel_launch(void* const* d_in, const int* in_sizes, int n_in,
                              void* d_out, int out_size) {
    const float* x    = (const float*)d_in[0];
    const float* etc0 = (const float*)d_in[1];
    const float* otc0 = (const float*)d_in[2];
    const float* etc1 = (const float*)d_in[3];
    const float* otc1 = (const float*)d_in[4];
    float* out = (float*)d_out;

    uint32_t l0k0, l0k1, l1k0, l1k1;
    tf2x32(0u, 42u, 0u, 0u, l0k0, l0k1);
    tf2x32(0u, 42u, 0u, 1u, l1k0, l1k1);
    uint32_t op0k0, op0k1, e0k0, e0k1;
    tf2x32(l0k0, l0k1, 0u, 0u, op0k0, op0k1);
    tf2x32(l0k0, l0k1, 0u, 1u, e0k0,  e0k1);
    uint32_t op1k0, op1k1, e1k0, e1k1;
    tf2x32(l1k0, l1k1, 0u, 0u, op1k0, op1k1);
    tf2x32(l1k0, l1k1, 0u, 1u, e1k0,  e1k1);

    k_masks<<<512, 512>>>(etc0, otc0, etc1, otc1,
                          op0k0, op0k1, e0k0, e0k1,
                          op1k0, op1k1, e1k0, e1k1);
    k_fused<<<B_SZ, 512>>>(x, out);
}

// round 14
// speedup vs baseline: 1.0168x; 1.0168x over previous
#include <cuda_runtime.h>
#include <cstdint>

// ---------------------------------------------------------------------------
// Threefry-2x32, FULL 20 rounds + 6 key injections (bit-exact JAX).
// ---------------------------------------------------------------------------
#define TF_ROUND(r) do { x0 += x1; x1 = (x1 << (r)) | (x1 >> (32 - (r))); x1 ^= x0; } while (0)

__host__ __device__ __forceinline__ void tf2x32(uint32_t k0, uint32_t k1,
                                                uint32_t x0, uint32_t x1,
                                                uint32_t& o0, uint32_t& o1) {
    uint32_t k2 = k0 ^ k1 ^ 0x1BD11BDAu;
    x0 += k0; x1 += k1;
    TF_ROUND(13); TF_ROUND(15); TF_ROUND(26); TF_ROUND(6);
    x0 += k1; x1 += k2 + 1u;
    TF_ROUND(17); TF_ROUND(29); TF_ROUND(16); TF_ROUND(24);
    x0 += k2; x1 += k0 + 2u;
    TF_ROUND(13); TF_ROUND(15); TF_ROUND(26); TF_ROUND(6);
    x0 += k0; x1 += k1 + 3u;
    TF_ROUND(17); TF_ROUND(29); TF_ROUND(16); TF_ROUND(24);
    x0 += k1; x1 += k2 + 4u;
    TF_ROUND(13); TF_ROUND(15); TF_ROUND(26); TF_ROUND(6);
    x0 += k2; x1 += k0 + 5u;
    o0 = x0; o1 = x1;
}

__device__ __forceinline__ uint32_t tfbits(uint32_t k0, uint32_t k1, uint32_t j) {
    uint32_t o0, o1;
    tf2x32(k0, k1, 0u, j, o0, o1);
    return o0 ^ o1;
}

__device__ __forceinline__ float jax_uniform(uint32_t bits) {
    const float TINY = 1.17549435e-38f;
    float f = __uint_as_float((bits >> 9) | 0x3f800000u) - 1.0f;
    return fmaxf(TINY, f + TINY);
}

__device__ __forceinline__ bool decide(float c0, float c1, uint32_t b0, uint32_t b1) {
    if (c0 == c1) return (b1 >> 9) > (b0 >> 9);
    float g0 = -logf(-logf(jax_uniform(b0)));
    float g1 = -logf(-logf(jax_uniform(b1)));
    return (c1 + g1) > (c0 + g0);
}

// ---------------------------------------------------------------------------
#define B_SZ  128
#define F0    1024
#define F1    512

__device__ int      g_op0[F1];
__device__ int      g_op1[F0];
// masks TRANSPOSED: g_mask0[w][o] (w<32,o<512), g_mask1[w][o] (w<16,o<1024)
__device__ uint32_t g_mask0[(F0 / 32) * F1];   // 64 KB
__device__ uint32_t g_mask1[(F1 / 32) * F0];   // 64 KB
__device__ unsigned g_cnt[2];                  // completion counters (memset per launch)

// shfl compare-exchange for one (k, j<=16) bitonic phase; s = element index.
__device__ __forceinline__ unsigned long long bitonic_shfl_step(
        unsigned long long v, int s, int k, int j) {
    unsigned long long pv = __shfl_xor_sync(0xffffffffu, v, j);
    bool up = ((s & k) == 0);
    bool keepMin = (((s & j) == 0) == up);
    unsigned long long lo = v < pv ? v : pv;
    unsigned long long hi = v < pv ? pv : v;
    return keepMin ? lo : hi;
}

// Batched per-thread probe; masks from global, transposed [w][o]:
// w warp-uniform, o lane-linear -> fully coalesced LDG (L2-hot).
__device__ __forceinline__ float probe8g(const unsigned long long* __restrict__ a,
                                         int n, const uint32_t* __restrict__ mt,
                                         int outn, int o, int op) {
    float res;
    if (op == 0) {
        res = 1.0f;
        for (int base = 0; base < n; base += 8) {
            unsigned long long kv[8];
            uint32_t w[8];
            #pragma unroll
            for (int t = 0; t < 8; ++t) kv[t] = a[base + t];
            #pragma unroll
            for (int t = 0; t < 8; ++t) {
                unsigned idx = (unsigned)kv[t];
                w[t] = mt[(idx >> 5) * outn + o] >> (idx & 31);
            }
            bool found = false;
            #pragma unroll
            for (int t = 0; t < 8; ++t)
                if (!found && (w[t] & 1u)) {
                    res = __uint_as_float((unsigned)(kv[t] >> 32));
                    found = true;
                }
            if (found) break;
        }
    } else {
        res = 0.0f;
        for (int base = n - 8; base >= 0; base -= 8) {
            unsigned long long kv[8];
            uint32_t w[8];
            #pragma unroll
            for (int t = 0; t < 8; ++t) kv[t] = a[base + 7 - t];
            #pragma unroll
            for (int t = 0; t < 8; ++t) {
                unsigned idx = (unsigned)kv[t];
                w[t] = mt[(idx >> 5) * outn + o] >> (idx & 31);
            }
            bool found = false;
            #pragma unroll
            for (int t = 0; t < 8; ++t)
                if (!found && (w[t] & 1u)) {
                    res = __uint_as_float((unsigned)(kv[t] >> 32));
                    found = true;
                }
            if (found) break;
        }
    }
    return res;
}

// spin until g_cnt[which] reaches target (thread 0 only), then block-sync.
__device__ __forceinline__ void wait_flag(int which, unsigned target, int tid) {
    if (tid == 0) {
        while (atomicAdd(&g_cnt[which], 0u) < target) __nanosleep(64);
    }
    __syncthreads();
    __threadfence();
}

// ---------------------------------------------------------------------------
// ONE kernel, 384 blocks x 512 threads (all co-resident; spin-wait safe):
//   blocks [0,128)   : fused per-row pipeline (sort1024 -> probe0 -> sort512 -> probe1)
//   blocks [128,256) : layer-0 masks -> g_cnt[0]
//   blocks [256,384) : layer-1 masks -> g_cnt[1]
// ---------------------------------------------------------------------------
__global__ __launch_bounds__(512) void all_kernel(
        const float* __restrict__ x, float* __restrict__ out,
        const float* __restrict__ etc0, const float* __restrict__ otc0,
        const float* __restrict__ etc1, const float* __restrict__ otc1,
        uint32_t op0k0, uint32_t op0k1, uint32_t e0k0, uint32_t e0k1,
        uint32_t op1k0, uint32_t op1k1, uint32_t e1k0, uint32_t e1k1) {
    int bid = blockIdx.x;
    int tid = threadIdx.x;

    if (bid >= B_SZ) {
        // ------------------ mask blocks ------------------
        int warp = tid >> 5, lane = tid & 31;
        int o, wslice, log2in, outn, which;
        const float* etc; const float* otc;
        uint32_t ek0, ek1, opk0, opk1;
        uint32_t* maskb; int* oparr;
        if (bid < 256) {          // layer 0: out=512; 4 neurons/block, 4 slices, 8 edges
            int q = bid - 128;    // 0..127
            o = q * 4 + (warp >> 2); wslice = warp & 3;
            log2in = 10; outn = F1; etc = etc0; otc = otc0;
            ek0 = e0k0; ek1 = e0k1; opk0 = op0k0; opk1 = op0k1;
            maskb = g_mask0; oparr = g_op0; which = 0;
        } else {                  // layer 1: out=1024; 8 neurons/block, 2 slices, 8 edges
            int q = bid - 256;    // 0..127
            o = q * 8 + (warp >> 1); wslice = warp & 1;
            log2in = 9; outn = F0; etc = etc1; otc = otc1;
            ek0 = e1k0; ek1 = e1k1; opk0 = op1k0; opk1 = op1k1;
            maskb = g_mask1; oparr = g_op1; which = 1;
        }

        uint32_t jv = tfbits(opk0, opk1, (uint32_t)(2 * o) + (uint32_t)(lane & 1));
        uint32_t ob0 = __shfl_sync(0xffffffffu, jv, 0);
        uint32_t ob1 = __shfl_sync(0xffffffffu, jv, 1);
        int op = decide(otc[2 * o], otc[2 * o + 1], ob0, ob1) ? 1 : 0;
        if (wslice == 0 && lane == 0) oparr[o] = op;

        uint32_t mbase = ((uint32_t)(o * 2 + op)) << log2in;
        const float2* etc2 = (const float2*)etc;

        #pragma unroll
        for (int c = 0; c < 8; ++c) {
            int i = wslice * 256 + c * 32 + lane;
            uint32_t m = mbase + (uint32_t)i;
            uint32_t b0 = tfbits(ek0, ek1, 2u * m);
            uint32_t b1 = tfbits(ek0, ek1, 2u * m + 1u);
            float2 cc = etc2[m];
            bool sel = decide(cc.x, cc.y, b0, b1);
            unsigned msk = __ballot_sync(0xffffffffu, sel);
            if (lane == 0) maskb[(i >> 5) * outn + o] = msk;   // transposed
        }

        __syncthreads();
        __threadfence();                       // release mask writes
        if (tid == 0) atomicAdd(&g_cnt[which], 1u);
        return;
    }

    // ------------------ fused blocks ------------------
    __shared__ unsigned long long a[1024];
    __shared__ unsigned long long hk[512];
    int row = bid;

    // 1) load + build keys (2 per thread)
    float v0 = fmaxf(x[(size_t)row * F0 + tid], 0.0f);
    float v1 = fmaxf(x[(size_t)row * F0 + tid + 512], 0.0f);
    unsigned long long e0 = ((unsigned long long)__float_as_uint(v0) << 32) | (unsigned)tid;
    unsigned long long e1 = ((unsigned long long)__float_as_uint(v1) << 32) | (unsigned)(tid + 512);

    // 2) bitonic 1024 (hybrid shfl) — overlaps with mask blocks chip-wide
    #pragma unroll
    for (int k = 2; k <= 32; k <<= 1)
        #pragma unroll
        for (int j = k >> 1; j > 0; j >>= 1) {
            e0 = bitonic_shfl_step(e0, tid, k, j);
            e1 = bitonic_shfl_step(e1, tid + 512, k, j);
        }
    a[tid] = e0; a[tid + 512] = e1;
    __syncthreads();

    #pragma unroll
    for (int k = 64; k <= 512; k <<= 1) {
        for (int j = k >> 1; j >= 32; j >>= 1) {
            #pragma unroll
            for (int r = 0; r < 2; ++r) {
                int s = tid + r * 512;
                int l = s ^ j;
                if (l > s) {
                    bool up = ((s & k) == 0);
                    unsigned long long va = a[s], vb = a[l];
                    if ((va > vb) == up) { a[s] = vb; a[l] = va; }
                }
            }
            __syncthreads();
        }
        e0 = a[tid]; e1 = a[tid + 512];
        #pragma unroll
        for (int j = 16; j > 0; j >>= 1) {
            e0 = bitonic_shfl_step(e0, tid, k, j);
            e1 = bitonic_shfl_step(e1, tid + 512, k, j);
        }
        a[tid] = e0; a[tid + 512] = e1;
        __syncthreads();
    }

    e0 = a[tid]; e1 = a[tid + 512];
    if (e0 > e1) { unsigned long long t = e0; e0 = e1; e1 = t; }
    a[tid] = e0; a[tid + 512] = e1;
    __syncthreads();
    for (int j = 256; j >= 32; j >>= 1) {
        #pragma unroll
        for (int r = 0; r < 2; ++r) {
            int s = tid + r * 512;
            int l = s ^ j;
            if (l > s) {
                unsigned long long va = a[s], vb = a[l];
                if (va > vb) { a[s] = vb; a[l] = va; }
            }
        }
        __syncthreads();
    }
    e0 = a[tid]; e1 = a[tid + 512];
    #pragma unroll
    for (int j = 16; j > 0; j >>= 1) {
        e0 = bitonic_shfl_step(e0, tid, 1024, j);
        e1 = bitonic_shfl_step(e1, tid + 512, 1024, j);
    }
    a[tid] = e0; a[tid + 512] = e1;

    // 3) wait for layer-0 masks, then probe layer 0
    wait_flag(0, 128, tid);
    unsigned long long v;
    {
        int o = tid;
        int op = g_op0[o];
        float res = probe8g(a, F0, g_mask0, F1, o, op);
        v = ((unsigned long long)__float_as_uint(res) << 32) | (unsigned)o;
    }

    // 4) bitonic sort 512 hidden keys
    #pragma unroll
    for (int k = 2; k <= 32; k <<= 1)
        #pragma unroll
        for (int j = k >> 1; j > 0; j >>= 1)
            v = bitonic_shfl_step(v, tid, k, j);

    hk[tid] = v;
    __syncthreads();

    #pragma unroll
    for (int k = 64; k <= 512; k <<= 1) {
        for (int j = k >> 1; j >= 32; j >>= 1) {
            int s = tid, l = tid ^ j;
            if (l > s) {
                bool up = ((s & k) == 0);
                unsigned long long va = hk[s], vb = hk[l];
                if ((va > vb) == up) { hk[s] = vb; hk[l] = va; }
            }
            __syncthreads();
        }
        v = hk[tid];
        #pragma unroll
        for (int j = 16; j > 0; j >>= 1)
            v = bitonic_shfl_step(v, tid, k, j);
        hk[tid] = v;
        __syncthreads();
    }

    // 5) wait for layer-1 masks, then probe layer 1 -> out
    wait_flag(1, 128, tid);
    #pragma unroll
    for (int rep = 0; rep < 2; ++rep) {
        int o = tid + rep * 512;
        int op = g_op1[o];
        float res = probe8g(hk, F1, g_mask1, F0, o, op);
        out[(size_t)row * F0 + o] = res;
    }
}

// ---------------------------------------------------------------------------
extern "C" void kernel_launch(void* const* d_in, const int* in_sizes, int n_in,
                              void* d_out, int out_size) {
    const float* x    = (const float*)d_in[0];
    const float* etc0 = (const float*)d_in[1];
    const float* otc0 = (const float*)d_in[2];
    const float* etc1 = (const float*)d_in[3];
    const float* otc1 = (const float*)d_in[4];
    float* out = (float*)d_out;

    uint32_t l0k0, l0k1, l1k0, l1k1;
    tf2x32(0u, 42u, 0u, 0u, l0k0, l0k1);
    tf2x32(0u, 42u, 0u, 1u, l1k0, l1k1);
    uint32_t op0k0, op0k1, e0k0, e0k1;
    tf2x32(l0k0, l0k1, 0u, 0u, op0k0, op0k1);
    tf2x32(l0k0, l0k1, 0u, 1u, e0k0,  e0k1);
    uint32_t op1k0, op1k1, e1k0, e1k1;
    tf2x32(l1k0, l1k1, 0u, 0u, op1k0, op1k1);
    tf2x32(l1k0, l1k1, 0u, 1u, e1k0,  e1k1);

    void* p_cnt;
    cudaGetSymbolAddress(&p_cnt, g_cnt);
    cudaMemsetAsync(p_cnt, 0, 2 * sizeof(unsigned));   // capture-safe memset node

    all_kernel<<<384, 512>>>(x, out, etc0, otc0, etc1, otc1,
                             op0k0, op0k1, e0k0, e0k1,
                             op1k0, op1k1, e1k0, e1k1);
}

// round 15
// speedup vs baseline: 1.0722x; 1.0544x over previous
#include <cuda_runtime.h>
#include <cstdint>

// ---------------------------------------------------------------------------
// Threefry-2x32, FULL 20 rounds + 6 key injections (bit-exact JAX).
// ---------------------------------------------------------------------------
#define TF_ROUND(r) do { x0 += x1; x1 = (x1 << (r)) | (x1 >> (32 - (r))); x1 ^= x0; } while (0)

__host__ __device__ __forceinline__ void tf2x32(uint32_t k0, uint32_t k1,
                                                uint32_t x0, uint32_t x1,
                                                uint32_t& o0, uint32_t& o1) {
    uint32_t k2 = k0 ^ k1 ^ 0x1BD11BDAu;
    x0 += k0; x1 += k1;
    TF_ROUND(13); TF_ROUND(15); TF_ROUND(26); TF_ROUND(6);
    x0 += k1; x1 += k2 + 1u;
    TF_ROUND(17); TF_ROUND(29); TF_ROUND(16); TF_ROUND(24);
    x0 += k2; x1 += k0 + 2u;
    TF_ROUND(13); TF_ROUND(15); TF_ROUND(26); TF_ROUND(6);
    x0 += k0; x1 += k1 + 3u;
    TF_ROUND(17); TF_ROUND(29); TF_ROUND(16); TF_ROUND(24);
    x0 += k1; x1 += k2 + 4u;
    TF_ROUND(13); TF_ROUND(15); TF_ROUND(26); TF_ROUND(6);
    x0 += k2; x1 += k0 + 5u;
    o0 = x0; o1 = x1;
}

__device__ __forceinline__ uint32_t tfbits(uint32_t k0, uint32_t k1, uint32_t j) {
    uint32_t o0, o1;
    tf2x32(k0, k1, 0u, j, o0, o1);
    return o0 ^ o1;
}

__device__ __forceinline__ float jax_uniform(uint32_t bits) {
    const float TINY = 1.17549435e-38f;
    float f = __uint_as_float((bits >> 9) | 0x3f800000u) - 1.0f;
    return fmaxf(TINY, f + TINY);
}

__device__ __forceinline__ bool decide(float c0, float c1, uint32_t b0, uint32_t b1) {
    if (c0 == c1) return (b1 >> 9) > (b0 >> 9);
    float g0 = -logf(-logf(jax_uniform(b0)));
    float g1 = -logf(-logf(jax_uniform(b1)));
    return (c1 + g1) > (c0 + g0);
}

// ---------------------------------------------------------------------------
#define B_SZ  128
#define F0    1024
#define F1    512

__device__ int      g_op0[F1];
__device__ int      g_op1[F0];
// masks TRANSPOSED: g_mask0[w][o] (w<32,o<512), g_mask1[w][o] (w<16,o<1024)
__device__ uint32_t g_mask0[(F0 / 32) * F1];   // 64 KB
__device__ uint32_t g_mask1[(F1 / 32) * F0];   // 64 KB

// shfl compare-exchange for one (k, j<=16) bitonic phase; s = element index.
__device__ __forceinline__ unsigned long long bitonic_shfl_step(
        unsigned long long v, int s, int k, int j) {
    unsigned long long pv = __shfl_xor_sync(0xffffffffu, v, j);
    bool up = ((s & k) == 0);
    bool keepMin = (((s & j) == 0) == up);
    unsigned long long lo = v < pv ? v : pv;
    unsigned long long hi = v < pv ? pv : v;
    return keepMin ? lo : hi;
}

// ---------------------------------------------------------------------------
// k_masks (256 blocks, 512 threads): pure threefry mask generation, 1 wave.
//   blocks [0,128)   : layer-0 masks (out=512: 4 neurons/blk, 4 slices, 8 edges)
//   blocks [128,256) : layer-1 masks (out=1024: 8 neurons/blk, 2 slices, 8 edges)
// ---------------------------------------------------------------------------
__global__ __launch_bounds__(512) void k_masks(
        const float* __restrict__ etc0, const float* __restrict__ otc0,
        const float* __restrict__ etc1, const float* __restrict__ otc1,
        uint32_t op0k0, uint32_t op0k1, uint32_t e0k0, uint32_t e0k1,
        uint32_t op1k0, uint32_t op1k1, uint32_t e1k0, uint32_t e1k1) {
    int bid = blockIdx.x;
    int tid = threadIdx.x;
    int warp = tid >> 5, lane = tid & 31;

    int o, wslice, log2in, outn;
    const float* etc; const float* otc;
    uint32_t ek0, ek1, opk0, opk1;
    uint32_t* maskb; int* oparr;
    if (bid < 128) {
        o = bid * 4 + (warp >> 2); wslice = warp & 3;
        log2in = 10; outn = F1; etc = etc0; otc = otc0;
        ek0 = e0k0; ek1 = e0k1; opk0 = op0k0; opk1 = op0k1;
        maskb = g_mask0; oparr = g_op0;
    } else {
        int q = bid - 128;
        o = q * 8 + (warp >> 1); wslice = warp & 1;
        log2in = 9; outn = F0; etc = etc1; otc = otc1;
        ek0 = e1k0; ek1 = e1k1; opk0 = op1k0; opk1 = op1k1;
        maskb = g_mask1; oparr = g_op1;
    }

    uint32_t jv = tfbits(opk0, opk1, (uint32_t)(2 * o) + (uint32_t)(lane & 1));
    uint32_t ob0 = __shfl_sync(0xffffffffu, jv, 0);
    uint32_t ob1 = __shfl_sync(0xffffffffu, jv, 1);
    int op = decide(otc[2 * o], otc[2 * o + 1], ob0, ob1) ? 1 : 0;
    if (wslice == 0 && lane == 0) oparr[o] = op;

    uint32_t mbase = ((uint32_t)(o * 2 + op)) << log2in;
    const float2* etc2 = (const float2*)etc;

    #pragma unroll
    for (int c = 0; c < 8; ++c) {
        int i = wslice * 256 + c * 32 + lane;
        uint32_t m = mbase + (uint32_t)i;
        uint32_t b0 = tfbits(ek0, ek1, 2u * m);
        uint32_t b1 = tfbits(ek0, ek1, 2u * m + 1u);
        float2 cc = etc2[m];
        bool sel = decide(cc.x, cc.y, b0, b1);
        unsigned msk = __ballot_sync(0xffffffffu, sel);
        if (lane == 0) maskb[(i >> 5) * outn + o] = msk;   // transposed
    }
}

// ---------------------------------------------------------------------------
// Batched per-thread probe; masks from global, transposed [w][o]:
// w warp-uniform, o lane-linear -> fully coalesced LDG (L2-hot).
// ---------------------------------------------------------------------------
__device__ __forceinline__ float probe8g(const unsigned long long* __restrict__ a,
                                         int n, const uint32_t* __restrict__ mt,
                                         int outn, int o, int op) {
    float res;
    if (op == 0) {
        res = 1.0f;
        for (int base = 0; base < n; base += 8) {
            unsigned long long kv[8];
            uint32_t w[8];
            #pragma unroll
            for (int t = 0; t < 8; ++t) kv[t] = a[base + t];
            #pragma unroll
            for (int t = 0; t < 8; ++t) {
                unsigned idx = (unsigned)kv[t];
                w[t] = __ldg(mt + (idx >> 5) * outn + o) >> (idx & 31);
            }
            bool found = false;
            #pragma unroll
            for (int t = 0; t < 8; ++t)
                if (!found && (w[t] & 1u)) {
                    res = __uint_as_float((unsigned)(kv[t] >> 32));
                    found = true;
                }
            if (found) break;
        }
    } else {
        res = 0.0f;
        for (int base = n - 8; base >= 0; base -= 8) {
            unsigned long long kv[8];
            uint32_t w[8];
            #pragma unroll
            for (int t = 0; t < 8; ++t) kv[t] = a[base + 7 - t];
            #pragma unroll
            for (int t = 0; t < 8; ++t) {
                unsigned idx = (unsigned)kv[t];
                w[t] = __ldg(mt + (idx >> 5) * outn + o) >> (idx & 31);
            }
            bool found = false;
            #pragma unroll
            for (int t = 0; t < 8; ++t)
                if (!found && (w[t] & 1u)) {
                    res = __uint_as_float((unsigned)(kv[t] >> 32));
                    found = true;
                }
            if (found) break;
        }
    }
    return res;
}

// ---------------------------------------------------------------------------
// k_fused (128 blocks, 1024 threads): per batch row:
//  1) load raw x row, build keys (1/thread)
//  2) bitonic sort 1024 (1 elem/thread: reg shfl k<=32, smem j>=32, reg j<=16)
//  3) probe layer 0 (tid<512, 1 neuron/thread)
//  4) bitonic sort 512 hidden keys (tid<512)
//  5) probe layer 1 (1 neuron/thread) -> out
// ---------------------------------------------------------------------------
__global__ __launch_bounds__(1024) void k_fused(const float* __restrict__ x,
                                                float* __restrict__ out) {
    __shared__ unsigned long long a[1024];
    __shared__ unsigned long long hk[512];
    int row = blockIdx.x;
    int tid = threadIdx.x;

    // 1) load + build key
    float vx = fmaxf(x[(size_t)row * F0 + tid], 0.0f);
    unsigned long long e = ((unsigned long long)__float_as_uint(vx) << 32) | (unsigned)tid;

    // 2a) k = 2..32 in registers
    #pragma unroll
    for (int k = 2; k <= 32; k <<= 1)
        #pragma unroll
        for (int j = k >> 1; j > 0; j >>= 1)
            e = bitonic_shfl_step(e, tid, k, j);
    a[tid] = e;
    __syncthreads();

    // 2b) k = 64..1024: j>=32 in smem, j<=16 in registers
    #pragma unroll
    for (int k = 64; k <= 1024; k <<= 1) {
        for (int j = k >> 1; j >= 32; j >>= 1) {
            int l = tid ^ j;
            if (l > tid) {
                bool up = ((tid & k) == 0);
                unsigned long long va = a[tid], vb = a[l];
                if ((va > vb) == up) { a[tid] = vb; a[l] = va; }
            }
            __syncthreads();
        }
        e = a[tid];
        #pragma unroll
        for (int j = 16; j > 0; j >>= 1)
            e = bitonic_shfl_step(e, tid, k, j);
        a[tid] = e;
        __syncthreads();
    }

    // 3) probe layer 0 (tid < 512)
    unsigned long long v = 0;
    if (tid < F1) {
        int o = tid;
        int op = g_op0[o];
        float res = probe8g(a, F0, g_mask0, F1, o, op);
        v = ((unsigned long long)__float_as_uint(res) << 32) | (unsigned)o;

        // 4a) sort512: k = 2..32 in registers (warps 0..15 only, full warps)
        #pragma unroll
        for (int k = 2; k <= 32; k <<= 1)
            #pragma unroll
            for (int j = k >> 1; j > 0; j >>= 1)
                v = bitonic_shfl_step(v, tid, k, j);
        hk[tid] = v;
    }
    __syncthreads();

    // 4b) k = 64..512: smem phases + register sub-steps (tid < 512)
    #pragma unroll
    for (int k = 64; k <= 512; k <<= 1) {
        for (int j = k >> 1; j >= 32; j >>= 1) {
            if (tid < F1) {
                int l = tid ^ j;
                if (l > tid) {
                    bool up = ((tid & k) == 0);
                    unsigned long long va = hk[tid], vb = hk[l];
                    if ((va > vb) == up) { hk[tid] = vb; hk[l] = va; }
                }
            }
            __syncthreads();
        }
        if (tid < F1) {
            v = hk[tid];
            #pragma unroll
            for (int j = 16; j > 0; j >>= 1)
                v = bitonic_shfl_step(v, tid, k, j);
            hk[tid] = v;
        }
        __syncthreads();
    }

    // 5) probe layer 1 (1 neuron per thread) -> out
    {
        int o = tid;
        int op = g_op1[o];
        float res = probe8g(hk, F1, g_mask1, F0, o, op);
        out[(size_t)row * F0 + o] = res;
    }
}

// ---------------------------------------------------------------------------
extern "C" void kernel_launch(void* const* d_in, const int* in_sizes, int n_in,
                              void* d_out, int out_size) {
    const float* x    = (const float*)d_in[0];
    const float* etc0 = (const float*)d_in[1];
    const float* otc0 = (const float*)d_in[2];
    const float* etc1 = (const float*)d_in[3];
    const float* otc1 = (const float*)d_in[4];
    float* out = (float*)d_out;

    uint32_t l0k0, l0k1, l1k0, l1k1;
    tf2x32(0u, 42u, 0u, 0u, l0k0, l0k1);
    tf2x32(0u, 42u, 0u, 1u, l1k0, l1k1);
    uint32_t op0k0, op0k1, e0k0, e0k1;
    tf2x32(l0k0, l0k1, 0u, 0u, op0k0, op0k1);
    tf2x32(l0k0, l0k1, 0u, 1u, e0k0,  e0k1);
    uint32_t op1k0, op1k1, e1k0, e1k1;
    tf2x32(l1k0, l1k1, 0u, 0u, op1k0, op1k1);
    tf2x32(l1k0, l1k1, 0u, 1u, e1k0,  e1k1);

    k_masks<<<256, 512>>>(etc0, otc0, etc1, otc1,
                          op0k0, op0k1, e0k0, e0k1,
                          op1k0, op1k1, e1k0, e1k1);
    k_fused<<<B_SZ, 1024>>>(x, out);
}

// round 16
// speedup vs baseline: 1.1000x; 1.0260x over previous
#include <cuda_runtime.h>
#include <cstdint>

// ---------------------------------------------------------------------------
// Threefry-2x32, FULL 20 rounds + 6 key injections (bit-exact JAX).
// ---------------------------------------------------------------------------
#define TF_ROUND(r) do { x0 += x1; x1 = (x1 << (r)) | (x1 >> (32 - (r))); x1 ^= x0; } while (0)

__host__ __device__ __forceinline__ void tf2x32(uint32_t k0, uint32_t k1,
                                                uint32_t x0, uint32_t x1,
                                                uint32_t& o0, uint32_t& o1) {
    uint32_t k2 = k0 ^ k1 ^ 0x1BD11BDAu;
    x0 += k0; x1 += k1;
    TF_ROUND(13); TF_ROUND(15); TF_ROUND(26); TF_ROUND(6);
    x0 += k1; x1 += k2 + 1u;
    TF_ROUND(17); TF_ROUND(29); TF_ROUND(16); TF_ROUND(24);
    x0 += k2; x1 += k0 + 2u;
    TF_ROUND(13); TF_ROUND(15); TF_ROUND(26); TF_ROUND(6);
    x0 += k0; x1 += k1 + 3u;
    TF_ROUND(17); TF_ROUND(29); TF_ROUND(16); TF_ROUND(24);
    x0 += k1; x1 += k2 + 4u;
    TF_ROUND(13); TF_ROUND(15); TF_ROUND(26); TF_ROUND(6);
    x0 += k2; x1 += k0 + 5u;
    o0 = x0; o1 = x1;
}

__device__ __forceinline__ uint32_t tfbits(uint32_t k0, uint32_t k1, uint32_t j) {
    uint32_t o0, o1;
    tf2x32(k0, k1, 0u, j, o0, o1);
    return o0 ^ o1;
}

__device__ __forceinline__ float jax_uniform(uint32_t bits) {
    const float TINY = 1.17549435e-38f;
    float f = __uint_as_float((bits >> 9) | 0x3f800000u) - 1.0f;
    return fmaxf(TINY, f + TINY);
}

__device__ __forceinline__ bool decide(float c0, float c1, uint32_t b0, uint32_t b1) {
    if (c0 == c1) return (b1 >> 9) > (b0 >> 9);
    float g0 = -logf(-logf(jax_uniform(b0)));
    float g1 = -logf(-logf(jax_uniform(b1)));
    return (c1 + g1) > (c0 + g0);
}

// ---------------------------------------------------------------------------
#define B_SZ  128
#define F0    1024
#define F1    512

__device__ int      g_op0[F1];
__device__ int      g_op1[F0];
// masks TRANSPOSED: g_mask0[w][o] (w<32,o<512), g_mask1[w][o] (w<16,o<1024)
__device__ uint32_t g_mask0[(F0 / 32) * F1];   // 64 KB
__device__ uint32_t g_mask1[(F1 / 32) * F0];   // 64 KB
__device__ unsigned g_cnt;                     // mask-completion counter

// named barrier for the 512 sort threads (warps 0..15)
#define NB512() asm volatile("bar.sync 1, 512;" ::: "memory")

// shfl compare-exchange for one (k, j<=16) bitonic phase; s = element index.
__device__ __forceinline__ unsigned long long bitonic_shfl_step(
        unsigned long long v, int s, int k, int j) {
    unsigned long long pv = __shfl_xor_sync(0xffffffffu, v, j);
    bool up = ((s & k) == 0);
    bool keepMin = (((s & j) == 0) == up);
    unsigned long long lo = v < pv ? v : pv;
    unsigned long long hi = v < pv ? pv : v;
    return keepMin ? lo : hi;
}

// Edge-mask slice: neuron o, warp-slice wslice, 8 edge-iterations of 32 lanes.
template <int LOG2IN>
__device__ __forceinline__ void gen_masks(int o, int wslice, int lane,
                                          const float* __restrict__ etc,
                                          const float* __restrict__ otc,
                                          uint32_t* __restrict__ maskb,
                                          int* __restrict__ oparr, int outn,
                                          uint32_t opk0, uint32_t opk1,
                                          uint32_t ek0, uint32_t ek1) {
    uint32_t jv = tfbits(opk0, opk1, (uint32_t)(2 * o) + (uint32_t)(lane & 1));
    uint32_t ob0 = __shfl_sync(0xffffffffu, jv, 0);
    uint32_t ob1 = __shfl_sync(0xffffffffu, jv, 1);
    int op = decide(otc[2 * o], otc[2 * o + 1], ob0, ob1) ? 1 : 0;
    if (wslice == 0 && lane == 0) oparr[o] = op;

    uint32_t mbase = ((uint32_t)(o * 2 + op)) << LOG2IN;
    const float2* etc2 = (const float2*)etc;
    #pragma unroll
    for (int c = 0; c < 8; ++c) {
        int i = wslice * 256 + c * 32 + lane;
        uint32_t m = mbase + (uint32_t)i;
        uint32_t b0 = tfbits(ek0, ek1, 2u * m);
        uint32_t b1 = tfbits(ek0, ek1, 2u * m + 1u);
        float2 cc = etc2[m];
        bool sel = decide(cc.x, cc.y, b0, b1);
        unsigned msk = __ballot_sync(0xffffffffu, sel);
        if (lane == 0) maskb[(i >> 5) * outn + o] = msk;   // transposed
    }
}

// Batched per-thread probe; masks from global, transposed [w][o]:
// w warp-uniform, o lane-linear -> fully coalesced LDG (L2-hot).
__device__ __forceinline__ float probe8g(const unsigned long long* __restrict__ a,
                                         int n, const uint32_t* __restrict__ mt,
                                         int outn, int o, int op) {
    float res;
    if (op == 0) {
        res = 1.0f;
        for (int base = 0; base < n; base += 8) {
            unsigned long long kv[8];
            uint32_t w[8];
            #pragma unroll
            for (int t = 0; t < 8; ++t) kv[t] = a[base + t];
            #pragma unroll
            for (int t = 0; t < 8; ++t) {
                unsigned idx = (unsigned)kv[t];
                w[t] = __ldg(mt + (idx >> 5) * outn + o) >> (idx & 31);
            }
            bool found = false;
            #pragma unroll
            for (int t = 0; t < 8; ++t)
                if (!found && (w[t] & 1u)) {
                    res = __uint_as_float((unsigned)(kv[t] >> 32));
                    found = true;
                }
            if (found) break;
        }
    } else {
        res = 0.0f;
        for (int base = n - 8; base >= 0; base -= 8) {
            unsigned long long kv[8];
            uint32_t w[8];
            #pragma unroll
            for (int t = 0; t < 8; ++t) kv[t] = a[base + 7 - t];
            #pragma unroll
            for (int t = 0; t < 8; ++t) {
                unsigned idx = (unsigned)kv[t];
                w[t] = __ldg(mt + (idx >> 5) * outn + o) >> (idx & 31);
            }
            bool found = false;
            #pragma unroll
            for (int t = 0; t < 8; ++t)
                if (!found && (w[t] & 1u)) {
                    res = __uint_as_float((unsigned)(kv[t] >> 32));
                    found = true;
                }
            if (found) break;
        }
    }
    return res;
}

// ---------------------------------------------------------------------------
// ONE kernel: 128 blocks x 1024 threads (1 block/SM, all co-resident).
// Warp-specialized phase 1:
//   warps 0..15  (tid<512): sort1024 (2 elem/thread) with named barrier
//   warps 16..31: this block's 1/128 slice of mask0 + mask1 -> g_cnt
// Then: wait all masks -> probe0 -> sort512 -> probe1.
// ---------------------------------------------------------------------------
__global__ __launch_bounds__(1024) void all_kernel(
        const float* __restrict__ x, float* __restrict__ out,
        const float* __restrict__ etc0, const float* __restrict__ otc0,
        const float* __restrict__ etc1, const float* __restrict__ otc1,
        uint32_t op0k0, uint32_t op0k1, uint32_t e0k0, uint32_t e0k1,
        uint32_t op1k0, uint32_t op1k1, uint32_t e1k0, uint32_t e1k1) {
    __shared__ unsigned long long a[1024];
    __shared__ unsigned long long hk[512];
    int bid = blockIdx.x;
    int tid = threadIdx.x;
    int warp = tid >> 5, lane = tid & 31;

    if (tid < 512) {
        // ---------------- sort warps: bitonic 1024, 2 elems/thread ----------
        float v0 = fmaxf(x[(size_t)bid * F0 + tid], 0.0f);
        float v1 = fmaxf(x[(size_t)bid * F0 + tid + 512], 0.0f);
        unsigned long long e0 = ((unsigned long long)__float_as_uint(v0) << 32) | (unsigned)tid;
        unsigned long long e1 = ((unsigned long long)__float_as_uint(v1) << 32) | (unsigned)(tid + 512);

        #pragma unroll
        for (int k = 2; k <= 32; k <<= 1)
            #pragma unroll
            for (int j = k >> 1; j > 0; j >>= 1) {
                e0 = bitonic_shfl_step(e0, tid, k, j);
                e1 = bitonic_shfl_step(e1, tid + 512, k, j);
            }
        a[tid] = e0; a[tid + 512] = e1;
        NB512();

        #pragma unroll
        for (int k = 64; k <= 512; k <<= 1) {
            for (int j = k >> 1; j >= 32; j >>= 1) {
                #pragma unroll
                for (int r = 0; r < 2; ++r) {
                    int s = tid + r * 512;
                    int l = s ^ j;
                    if (l > s) {
                        bool up = ((s & k) == 0);
                        unsigned long long va = a[s], vb = a[l];
                        if ((va > vb) == up) { a[s] = vb; a[l] = va; }
                    }
                }
                NB512();
            }
            e0 = a[tid]; e1 = a[tid + 512];
            #pragma unroll
            for (int j = 16; j > 0; j >>= 1) {
                e0 = bitonic_shfl_step(e0, tid, k, j);
                e1 = bitonic_shfl_step(e1, tid + 512, k, j);
            }
            a[tid] = e0; a[tid + 512] = e1;
            NB512();
        }

        // k = 1024
        e0 = a[tid]; e1 = a[tid + 512];
        if (e0 > e1) { unsigned long long t = e0; e0 = e1; e1 = t; }
        a[tid] = e0; a[tid + 512] = e1;
        NB512();
        for (int j = 256; j >= 32; j >>= 1) {
            #pragma unroll
            for (int r = 0; r < 2; ++r) {
                int s = tid + r * 512;
                int l = s ^ j;
                if (l > s) {
                    unsigned long long va = a[s], vb = a[l];
                    if (va > vb) { a[s] = vb; a[l] = va; }
                }
            }
            NB512();
        }
        e0 = a[tid]; e1 = a[tid + 512];
        #pragma unroll
        for (int j = 16; j > 0; j >>= 1) {
            e0 = bitonic_shfl_step(e0, tid, 1024, j);
            e1 = bitonic_shfl_step(e1, tid + 512, 1024, j);
        }
        a[tid] = e0; a[tid + 512] = e1;
    } else {
        // ---------------- mask warps: this block's slice of both layers -----
        int w = warp - 16;                    // 0..15
        // layer 0: neurons [bid*4, bid*4+4), 4 slices each
        gen_masks<10>(bid * 4 + (w >> 2), w & 3, lane, etc0, otc0,
                      g_mask0, g_op0, F1, op0k0, op0k1, e0k0, e0k1);
        // layer 1: neurons [bid*8, bid*8+8), 2 slices each
        gen_masks<9>(bid * 8 + (w >> 1), w & 1, lane, etc1, otc1,
                     g_mask1, g_op1, F0, op1k0, op1k1, e1k0, e1k1);
        __threadfence();                      // release mask writes
        if (w == 0 && lane == 0) atomicAdd(&g_cnt, 1u);
    }

    __syncthreads();                          // sort done + local masks flagged

    // wait for ALL blocks' masks
    if (tid == 0) {
        while (atomicAdd(&g_cnt, 0u) < (unsigned)B_SZ) __nanosleep(64);
    }
    __syncthreads();
    __threadfence();

    // ---------------- probe layer 0 (tid < 512) ----------------
    unsigned long long v = 0;
    if (tid < F1) {
        int o = tid;
        int op = g_op0[o];
        float res = probe8g(a, F0, g_mask0, F1, o, op);
        v = ((unsigned long long)__float_as_uint(res) << 32) | (unsigned)o;

        #pragma unroll
        for (int k = 2; k <= 32; k <<= 1)
            #pragma unroll
            for (int j = k >> 1; j > 0; j >>= 1)
                v = bitonic_shfl_step(v, tid, k, j);
        hk[tid] = v;
    }
    __syncthreads();

    // ---------------- sort 512 hidden keys ----------------
    #pragma unroll
    for (int k = 64; k <= 512; k <<= 1) {
        for (int j = k >> 1; j >= 32; j >>= 1) {
            if (tid < F1) {
                int l = tid ^ j;
                if (l > tid) {
                    bool up = ((tid & k) == 0);
                    unsigned long long va = hk[tid], vb = hk[l];
                    if ((va > vb) == up) { hk[tid] = vb; hk[l] = va; }
                }
            }
            __syncthreads();
        }
        if (tid < F1) {
            v = hk[tid];
            #pragma unroll
            for (int j = 16; j > 0; j >>= 1)
                v = bitonic_shfl_step(v, tid, k, j);
            hk[tid] = v;
        }
        __syncthreads();
    }

    // ---------------- probe layer 1 (1 neuron/thread) ----------------
    {
        int o = tid;
        int op = g_op1[o];
        float res = probe8g(hk, F1, g_mask1, F0, o, op);
        out[(size_t)bid * F0 + o] = res;
    }
}

// ---------------------------------------------------------------------------
extern "C" void kernel_launch(void* const* d_in, const int* in_sizes, int n_in,
                              void* d_out, int out_size) {
    const float* x    = (const float*)d_in[0];
    const float* etc0 = (const float*)d_in[1];
    const float* otc0 = (const float*)d_in[2];
    const float* etc1 = (const float*)d_in[3];
    const float* otc1 = (const float*)d_in[4];
    float* out = (float*)d_out;

    uint32_t l0k0, l0k1, l1k0, l1k1;
    tf2x32(0u, 42u, 0u, 0u, l0k0, l0k1);
    tf2x32(0u, 42u, 0u, 1u, l1k0, l1k1);
    uint32_t op0k0, op0k1, e0k0, e0k1;
    tf2x32(l0k0, l0k1, 0u, 0u, op0k0, op0k1);
    tf2x32(l0k0, l0k1, 0u, 1u, e0k0,  e0k1);
    uint32_t op1k0, op1k1, e1k0, e1k1;
    tf2x32(l1k0, l1k1, 0u, 0u, op1k0, op1k1);
    tf2x32(l1k0, l1k1, 0u, 1u, e1k0,  e1k1);

    void* p_cnt;
    cudaGetSymbolAddress(&p_cnt, g_cnt);
    cudaMemsetAsync(p_cnt, 0, sizeof(unsigned));   // capture-safe reset

    all_kernel<<<B_SZ, 1024>>>(x, out, etc0, otc0, etc1, otc1,
                               op0k0, op0k1, e0k0, e0k1,
                               op1k0, op1k1, e1k0, e1k1);
}